// round 1
// baseline (speedup 1.0000x reference)
#include <cuda_runtime.h>
#include <math.h>

// Problem constants (fixed by the reference): B=8, T=4096, C=1024, H=1024
#define BB 8
#define TT 4096
#define CC 1024
#define HH 1024

// Static device scratch (allocation inside kernel_launch is forbidden).
// Q,K,V: 3 x 128 MB.  S (scores): 512 MB.
__device__ float g_q[(long long)BB * TT * HH];
__device__ float g_k[(long long)BB * TT * HH];
__device__ float g_v[(long long)BB * TT * HH];
__device__ float g_s[(long long)BB * TT * (long long)TT];

// ---------------------------------------------------------------------------
// Tiled SGEMM:  C[M,N] = alpha * A[M,K] @ op(B)
//   TRANSB=true :  B is [N,K] row-major (NT gemm, dot of rows)  -> used for
//                  projections (x @ W^T) and scores (Q @ K^T)
//   TRANSB=false:  B is [K,N] row-major (NN gemm)               -> used for P @ V
// Block tile 128x128x16, 256 threads, 8x8 accumulator per thread.
// All dims here are multiples of the tile sizes, so no bounds checks.
// blockIdx.z = batch, with element strides sA/sB/sC.
// ---------------------------------------------------------------------------
template <bool TRANSB>
__global__ __launch_bounds__(256) void sgemm_kernel(
    const float* __restrict__ A, const float* __restrict__ B,
    float* __restrict__ C, int M, int N, int K,
    long long sA, long long sB, long long sC, float alpha)
{
    constexpr int BM = 128, BN = 128, BK = 16;
    __shared__ float As[BK][BM];
    __shared__ float Bs[BK][BN];

    A += (long long)blockIdx.z * sA;
    B += (long long)blockIdx.z * sB;
    C += (long long)blockIdx.z * sC;

    const int tid = threadIdx.x;
    const int bm = blockIdx.y * BM;
    const int bn = blockIdx.x * BN;
    const int tx = tid & 15;   // 0..15 -> 8 output cols each
    const int ty = tid >> 4;   // 0..15 -> 8 output rows each

    // Loader mapping for a 128x16 row-major tile (A, and B when TRANSB):
    // 512 float4 loads, 2 per thread.
    const int ar = tid >> 2;          // 0..63 (+64 on second pass)
    const int ac = (tid & 3) << 2;    // k-offset 0,4,8,12
    // Loader mapping for a 16x128 row-major tile (B when !TRANSB):
    const int br = tid >> 5;          // 0..7 (+8 on second pass)
    const int bc = (tid & 31) << 2;   // n-offset

    float acc[8][8];
    #pragma unroll
    for (int i = 0; i < 8; i++)
        #pragma unroll
        for (int j = 0; j < 8; j++) acc[i][j] = 0.0f;

    for (int k0 = 0; k0 < K; k0 += BK) {
        // --- load A tile (transpose into As[k][m]) ---
        #pragma unroll
        for (int p = 0; p < 2; p++) {
            const int r = ar + p * 64;
            float4 va = *reinterpret_cast<const float4*>(
                A + (long long)(bm + r) * K + k0 + ac);
            As[ac + 0][r] = va.x;
            As[ac + 1][r] = va.y;
            As[ac + 2][r] = va.z;
            As[ac + 3][r] = va.w;
        }
        // --- load B tile into Bs[k][n] ---
        if (TRANSB) {
            #pragma unroll
            for (int p = 0; p < 2; p++) {
                const int r = ar + p * 64;
                float4 vb = *reinterpret_cast<const float4*>(
                    B + (long long)(bn + r) * K + k0 + ac);
                Bs[ac + 0][r] = vb.x;
                Bs[ac + 1][r] = vb.y;
                Bs[ac + 2][r] = vb.z;
                Bs[ac + 3][r] = vb.w;
            }
        } else {
            #pragma unroll
            for (int p = 0; p < 2; p++) {
                const int r = br + p * 8;
                float4 vb = *reinterpret_cast<const float4*>(
                    B + (long long)(k0 + r) * N + bn + bc);
                *reinterpret_cast<float4*>(&Bs[r][bc]) = vb;
            }
        }
        __syncthreads();

        // --- compute ---
        #pragma unroll
        for (int k = 0; k < BK; k++) {
            float4 a0 = *reinterpret_cast<const float4*>(&As[k][ty * 8]);
            float4 a1 = *reinterpret_cast<const float4*>(&As[k][ty * 8 + 4]);
            float4 b0 = *reinterpret_cast<const float4*>(&Bs[k][tx * 8]);
            float4 b1 = *reinterpret_cast<const float4*>(&Bs[k][tx * 8 + 4]);
            float ra[8] = {a0.x, a0.y, a0.z, a0.w, a1.x, a1.y, a1.z, a1.w};
            float rb[8] = {b0.x, b0.y, b0.z, b0.w, b1.x, b1.y, b1.z, b1.w};
            #pragma unroll
            for (int i = 0; i < 8; i++)
                #pragma unroll
                for (int j = 0; j < 8; j++)
                    acc[i][j] = fmaf(ra[i], rb[j], acc[i][j]);
        }
        __syncthreads();
    }

    // --- epilogue ---
    #pragma unroll
    for (int i = 0; i < 8; i++) {
        const long long row = bm + ty * 8 + i;
        float4 o0, o1;
        o0.x = alpha * acc[i][0]; o0.y = alpha * acc[i][1];
        o0.z = alpha * acc[i][2]; o0.w = alpha * acc[i][3];
        o1.x = alpha * acc[i][4]; o1.y = alpha * acc[i][5];
        o1.z = alpha * acc[i][6]; o1.w = alpha * acc[i][7];
        *reinterpret_cast<float4*>(C + row * N + bn + tx * 8)     = o0;
        *reinterpret_cast<float4*>(C + row * N + bn + tx * 8 + 4) = o1;
    }
}

// ---------------------------------------------------------------------------
// In-place row softmax over rows of length TT (=4096). One block per row.
// Row is staged in shared memory: one global read + one global write per elem.
// ---------------------------------------------------------------------------
__global__ __launch_bounds__(256) void softmax_kernel(float* __restrict__ S)
{
    __shared__ float buf[TT];
    __shared__ float red[256];
    const long long row = blockIdx.x;
    float* p = S + row * (long long)TT;
    const int tid = threadIdx.x;

    float m = -INFINITY;
    for (int i = tid; i < TT; i += 256) {
        float4 v = *reinterpret_cast<const float4*>(p + 0) ;  // (unused, keep scalar path)
        (void)v;
        break;
    }
    // scalar staged load + running max
    m = -INFINITY;
    for (int i = tid; i < TT; i += 256) {
        float v = p[i];
        buf[i] = v;
        m = fmaxf(m, v);
    }
    red[tid] = m;
    __syncthreads();
    #pragma unroll
    for (int st = 128; st > 0; st >>= 1) {
        if (tid < st) red[tid] = fmaxf(red[tid], red[tid + st]);
        __syncthreads();
    }
    m = red[0];
    __syncthreads();

    float sum = 0.0f;
    for (int i = tid; i < TT; i += 256) {
        float e = __expf(buf[i] - m);
        buf[i] = e;
        sum += e;
    }
    red[tid] = sum;
    __syncthreads();
    #pragma unroll
    for (int st = 128; st > 0; st >>= 1) {
        if (tid < st) red[tid] += red[tid + st];
        __syncthreads();
    }
    const float inv = 1.0f / red[0];
    __syncthreads();

    for (int i = tid; i < TT; i += 256) p[i] = buf[i] * inv;
}

// ---------------------------------------------------------------------------
extern "C" void kernel_launch(void* const* d_in, const int* in_sizes, int n_in,
                              void* d_out, int out_size)
{
    const float* x  = (const float*)d_in[0];
    const float* Wq = (const float*)d_in[1];
    const float* Wk = (const float*)d_in[2];
    const float* Wv = (const float*)d_in[3];
    float* out = (float*)d_out;

    float *q, *k, *v, *s;
    cudaGetSymbolAddress((void**)&q, g_q);
    cudaGetSymbolAddress((void**)&k, g_k);
    cudaGetSymbolAddress((void**)&v, g_v);
    cudaGetSymbolAddress((void**)&s, g_s);

    const dim3 blk(256);
    const long long strideQKV = (long long)TT * HH;   // per-batch Q/K/V stride
    const long long strideS   = (long long)TT * TT;   // per-batch score stride

    // 1) Projections: Q/K/V[M=B*T, N=H] = x[M, C] @ W[H, C]^T
    {
        dim3 g(HH / 128, (BB * TT) / 128, 1);   // (8, 256, 1)
        sgemm_kernel<true><<<g, blk>>>(x, Wq, q, BB * TT, HH, CC, 0, 0, 0, 1.0f);
        sgemm_kernel<true><<<g, blk>>>(x, Wk, k, BB * TT, HH, CC, 0, 0, 0, 1.0f);
        sgemm_kernel<true><<<g, blk>>>(x, Wv, v, BB * TT, HH, CC, 0, 0, 0, 1.0f);
    }

    // 2) Scores: S_b[T,T] = (Q_b @ K_b^T) / sqrt(C)   (sqrt(1024) = 32, exact)
    {
        dim3 g(TT / 128, TT / 128, BB);         // (32, 32, 8)
        sgemm_kernel<true><<<g, blk>>>(q, k, s, TT, TT, HH,
                                       strideQKV, strideQKV, strideS,
                                       1.0f / 32.0f);
    }

    // 3) Row softmax in place over S
    softmax_kernel<<<BB * TT, 256>>>(s);

    // 4) Output: out_b[T,H] = P_b[T,T] @ V_b[T,H]
    {
        dim3 g(HH / 128, TT / 128, BB);         // (8, 32, 8)
        sgemm_kernel<false><<<g, blk>>>(s, v, out, TT, HH, TT,
                                        strideS, strideQKV, strideQKV, 1.0f);
    }
}

// round 3
// speedup vs baseline: 3.3307x; 3.3307x over previous
#include <cuda_runtime.h>
#include <cuda_bf16.h>
#include <math.h>
#include <stdint.h>

// Problem constants: B=8, T=4096, C=1024, H=1024
#define BB 8
#define TT 4096
#define CC 1024
#define HH 1024

typedef __nv_bfloat16 bf16;

// ---------------------------------------------------------------------------
// Static device scratch (no allocation allowed).
// ---------------------------------------------------------------------------
__device__ bf16 g_xh[(size_t)BB * TT * CC];
__device__ bf16 g_xl[(size_t)BB * TT * CC];
__device__ bf16 g_wqh[HH * CC], g_wql[HH * CC];
__device__ bf16 g_wkh[HH * CC], g_wkl[HH * CC];
__device__ bf16 g_wvh[HH * CC], g_wvl[HH * CC];
__device__ bf16 g_qh[(size_t)BB * TT * HH], g_ql[(size_t)BB * TT * HH];
__device__ bf16 g_kh[(size_t)BB * TT * HH], g_kl[(size_t)BB * TT * HH];
__device__ bf16 g_vh[(size_t)BB * TT * HH], g_vl[(size_t)BB * TT * HH];
// V transposed per batch: [b][h][t]
__device__ bf16 g_vth[(size_t)BB * HH * TT], g_vtl[(size_t)BB * HH * TT];
__device__ float g_s[(size_t)BB * TT * TT];
__device__ bf16 g_ph[(size_t)BB * TT * TT], g_pl[(size_t)BB * TT * TT];

// ---------------------------------------------------------------------------
// m16n8k16 bf16 MMA (base ISA, works on plain sm_103 target)
// ---------------------------------------------------------------------------
__device__ __forceinline__ void mma16816(float* c, const uint32_t* a,
                                         uint32_t b0, uint32_t b1)
{
    asm volatile(
        "mma.sync.aligned.m16n8k16.row.col.f32.bf16.bf16.f32 "
        "{%0,%1,%2,%3}, {%4,%5,%6,%7}, {%8,%9}, {%0,%1,%2,%3};"
        : "+f"(c[0]), "+f"(c[1]), "+f"(c[2]), "+f"(c[3])
        : "r"(a[0]), "r"(a[1]), "r"(a[2]), "r"(a[3]), "r"(b0), "r"(b1));
}

// ---------------------------------------------------------------------------
// bf16x3 NT GEMM:  D[M,N] = alpha * (A[M,K] @ B[N,K]^T)
// A,B as (hi,lo) bf16 pairs; D = Ah*Bh + Ah*Bl + Al*Bh in fp32 accum.
// CTA tile 128x128x32.  256 threads = 8 warps in 4(M) x 2(N).
// Smem rows padded to 40 bf16 (80 B): 16B-aligned STS + conflict-free LDS.
// EPI: 0 = fp32*alpha -> outF ;  1 = hi/lo bf16 -> outH/outL (row-major).
// A stride = K, B stride = K, C stride = N; batch via blockIdx.z strides.
// ---------------------------------------------------------------------------
template <int EPI>
__global__ __launch_bounds__(256) void gemm_mma_kernel(
    const bf16* __restrict__ Ah, const bf16* __restrict__ Al,
    const bf16* __restrict__ Bh, const bf16* __restrict__ Bl,
    float* __restrict__ outF, bf16* __restrict__ outH, bf16* __restrict__ outL,
    int M, int N, int K,
    long long sA, long long sB, long long sC, float alpha)
{
    // 4 tiles of 128 rows x 80 bytes = 10240 B each
    __shared__ __align__(16) unsigned char sm[4 * 10240];
    constexpr int T_AH = 0, T_AL = 10240, T_BH = 20480, T_BL = 30720;

    const int tid = threadIdx.x;
    const int wid = tid >> 5;
    const int lane = tid & 31;
    const int g = lane >> 2;      // group id (rows)
    const int t = lane & 3;       // thread-in-group (k pairs / n cols)
    const int wm = wid & 3;       // warp M index (0..3) -> rows wm*32
    const int wn = wid >> 2;      // warp N index (0..1) -> cols wn*64

    const long long bz = blockIdx.z;
    Ah += bz * sA;  Al += bz * sA;
    Bh += bz * sB;  Bl += bz * sB;

    const int bm = blockIdx.y * 128;
    const int bn = blockIdx.x * 128;
    const int nk = K >> 5;        // K / 32

    // global loader mapping: 512 uint4 slots per tile; thread owns tid, tid+256
    const int lrow = tid >> 2;          // 0..63 (+64 for second slot)
    const int lc4  = tid & 3;           // 8-bf16 chunk within 32-elem row
    const int sts0 = lrow * 80 + lc4 * 16;
    const int sts1 = sts0 + 64 * 80;

    float acc[2][8][4];
    #pragma unroll
    for (int mt = 0; mt < 2; mt++)
        #pragma unroll
        for (int nt = 0; nt < 8; nt++)
            #pragma unroll
            for (int i = 0; i < 4; i++) acc[mt][nt][i] = 0.0f;

    uint4 rAh[2], rAl[2], rBh[2], rBl[2];

    auto ldg_all = [&](int kt) {
        const size_t ao = (size_t)(bm + lrow) * K + (size_t)kt * 32 + lc4 * 8;
        const size_t bo = (size_t)(bn + lrow) * K + (size_t)kt * 32 + lc4 * 8;
        const size_t r2 = (size_t)64 * K;
        rAh[0] = *reinterpret_cast<const uint4*>(Ah + ao);
        rAh[1] = *reinterpret_cast<const uint4*>(Ah + ao + r2);
        rAl[0] = *reinterpret_cast<const uint4*>(Al + ao);
        rAl[1] = *reinterpret_cast<const uint4*>(Al + ao + r2);
        rBh[0] = *reinterpret_cast<const uint4*>(Bh + bo);
        rBh[1] = *reinterpret_cast<const uint4*>(Bh + bo + r2);
        rBl[0] = *reinterpret_cast<const uint4*>(Bl + bo);
        rBl[1] = *reinterpret_cast<const uint4*>(Bl + bo + r2);
    };

    ldg_all(0);

    for (int kt = 0; kt < nk; kt++) {
        // stage current chunk to smem
        *reinterpret_cast<uint4*>(sm + T_AH + sts0) = rAh[0];
        *reinterpret_cast<uint4*>(sm + T_AH + sts1) = rAh[1];
        *reinterpret_cast<uint4*>(sm + T_AL + sts0) = rAl[0];
        *reinterpret_cast<uint4*>(sm + T_AL + sts1) = rAl[1];
        *reinterpret_cast<uint4*>(sm + T_BH + sts0) = rBh[0];
        *reinterpret_cast<uint4*>(sm + T_BH + sts1) = rBh[1];
        *reinterpret_cast<uint4*>(sm + T_BL + sts0) = rBl[0];
        *reinterpret_cast<uint4*>(sm + T_BL + sts1) = rBl[1];
        __syncthreads();

        // prefetch next chunk (latency hidden under the MMAs below)
        if (kt + 1 < nk) ldg_all(kt + 1);

        // compute: 2 k-steps of 16
        #pragma unroll
        for (int ks = 0; ks < 2; ks++) {
            uint32_t ah[2][4], al[2][4];
            #pragma unroll
            for (int mt = 0; mt < 2; mt++) {
                const int arow = wm * 32 + mt * 16 + g;
                const unsigned char* pa = sm + arow * 80 + ks * 32 + t * 4;
                ah[mt][0] = *reinterpret_cast<const uint32_t*>(pa + T_AH);
                ah[mt][1] = *reinterpret_cast<const uint32_t*>(pa + T_AH + 8 * 80);
                ah[mt][2] = *reinterpret_cast<const uint32_t*>(pa + T_AH + 16);
                ah[mt][3] = *reinterpret_cast<const uint32_t*>(pa + T_AH + 8 * 80 + 16);
                al[mt][0] = *reinterpret_cast<const uint32_t*>(pa + T_AL);
                al[mt][1] = *reinterpret_cast<const uint32_t*>(pa + T_AL + 8 * 80);
                al[mt][2] = *reinterpret_cast<const uint32_t*>(pa + T_AL + 16);
                al[mt][3] = *reinterpret_cast<const uint32_t*>(pa + T_AL + 8 * 80 + 16);
            }
            #pragma unroll
            for (int nt = 0; nt < 8; nt++) {
                const int brow = wn * 64 + nt * 8 + g;
                const unsigned char* pb = sm + brow * 80 + ks * 32 + t * 4;
                const uint32_t bh0 = *reinterpret_cast<const uint32_t*>(pb + T_BH);
                const uint32_t bh1 = *reinterpret_cast<const uint32_t*>(pb + T_BH + 16);
                const uint32_t bl0 = *reinterpret_cast<const uint32_t*>(pb + T_BL);
                const uint32_t bl1 = *reinterpret_cast<const uint32_t*>(pb + T_BL + 16);
                #pragma unroll
                for (int mt = 0; mt < 2; mt++) {
                    mma16816(acc[mt][nt], ah[mt], bh0, bh1);
                    mma16816(acc[mt][nt], ah[mt], bl0, bl1);
                    mma16816(acc[mt][nt], al[mt], bh0, bh1);
                }
            }
        }
        __syncthreads();
    }

    // ---- epilogue ----
    #pragma unroll
    for (int mt = 0; mt < 2; mt++) {
        const int r0 = bm + wm * 32 + mt * 16 + g;
        #pragma unroll
        for (int nt = 0; nt < 8; nt++) {
            const int c0 = bn + wn * 64 + nt * 8 + 2 * t;
            if (EPI == 0) {
                float2 v0, v1;
                v0.x = alpha * acc[mt][nt][0]; v0.y = alpha * acc[mt][nt][1];
                v1.x = alpha * acc[mt][nt][2]; v1.y = alpha * acc[mt][nt][3];
                *reinterpret_cast<float2*>(outF + bz * sC + (size_t)r0 * N + c0) = v0;
                *reinterpret_cast<float2*>(outF + bz * sC + (size_t)(r0 + 8) * N + c0) = v1;
            } else {
                #pragma unroll
                for (int h = 0; h < 2; h++) {
                    const float v0 = acc[mt][nt][2 * h + 0];
                    const float v1 = acc[mt][nt][2 * h + 1];
                    bf16 h0 = __float2bfloat16(v0);
                    bf16 h1 = __float2bfloat16(v1);
                    bf16 l0 = __float2bfloat16(v0 - __bfloat162float(h0));
                    bf16 l1 = __float2bfloat16(v1 - __bfloat162float(h1));
                    __nv_bfloat162 hp; hp.x = h0; hp.y = h1;
                    __nv_bfloat162 lp; lp.x = l0; lp.y = l1;
                    const size_t off = (size_t)(r0 + 8 * h) * N + c0;
                    *reinterpret_cast<__nv_bfloat162*>(outH + off) = hp;
                    *reinterpret_cast<__nv_bfloat162*>(outL + off) = lp;
                }
            }
        }
    }
}

// ---------------------------------------------------------------------------
// fp32 -> (hi, lo) bf16 split, float4-vectorized.  n4 = n/4.
// ---------------------------------------------------------------------------
__global__ __launch_bounds__(256) void convert_hilo_kernel(
    const float4* __restrict__ in, __nv_bfloat162* __restrict__ h2,
    __nv_bfloat162* __restrict__ l2, long long n4)
{
    long long i = (long long)blockIdx.x * blockDim.x + threadIdx.x;
    if (i >= n4) return;
    float4 v = in[i];
    bf16 h0 = __float2bfloat16(v.x), h1 = __float2bfloat16(v.y);
    bf16 h2v = __float2bfloat16(v.z), h3 = __float2bfloat16(v.w);
    bf16 l0 = __float2bfloat16(v.x - __bfloat162float(h0));
    bf16 l1 = __float2bfloat16(v.y - __bfloat162float(h1));
    bf16 l2v = __float2bfloat16(v.z - __bfloat162float(h2v));
    bf16 l3 = __float2bfloat16(v.w - __bfloat162float(h3));
    __nv_bfloat162 a; a.x = h0; a.y = h1;
    __nv_bfloat162 b; b.x = h2v; b.y = h3;
    __nv_bfloat162 c; c.x = l0; c.y = l1;
    __nv_bfloat162 d; d.x = l2v; d.y = l3;
    h2[2 * i] = a; h2[2 * i + 1] = b;
    l2[2 * i] = c; l2[2 * i + 1] = d;
}

// ---------------------------------------------------------------------------
// Per-batch transpose of hi/lo V: out[b][h][t] = in[b][t][h]
// ---------------------------------------------------------------------------
__global__ __launch_bounds__(1024) void transpose_hilo_kernel(
    const bf16* __restrict__ ih, const bf16* __restrict__ il,
    bf16* __restrict__ oh, bf16* __restrict__ ol)
{
    __shared__ bf16 th[32][33];
    __shared__ bf16 tl[32][33];
    const int b = blockIdx.z;
    const int h0 = blockIdx.x * 32;
    const int t0 = blockIdx.y * 32;
    const int tx = threadIdx.x, ty = threadIdx.y;

    const size_t iin = ((size_t)b * TT + t0 + ty) * HH + h0 + tx;
    th[ty][tx] = ih[iin];
    tl[ty][tx] = il[iin];
    __syncthreads();
    const size_t iout = ((size_t)b * HH + h0 + ty) * TT + t0 + tx;
    oh[iout] = th[tx][ty];
    ol[iout] = tl[tx][ty];
}

// ---------------------------------------------------------------------------
// Row softmax over S (fp32, rows of TT) -> P as (hi, lo) bf16.
// ---------------------------------------------------------------------------
__global__ __launch_bounds__(256) void softmax_kernel(
    const float* __restrict__ S, bf16* __restrict__ Ph, bf16* __restrict__ Pl)
{
    __shared__ float buf[TT];
    __shared__ float red[256];
    const size_t row = blockIdx.x;
    const float4* p4 = reinterpret_cast<const float4*>(S + row * TT);
    const int tid = threadIdx.x;

    float m = -INFINITY;
    for (int i = tid; i < TT / 4; i += 256) {
        float4 v = p4[i];
        reinterpret_cast<float4*>(buf)[i] = v;
        m = fmaxf(m, fmaxf(fmaxf(v.x, v.y), fmaxf(v.z, v.w)));
    }
    red[tid] = m;
    __syncthreads();
    #pragma unroll
    for (int st = 128; st > 0; st >>= 1) {
        if (tid < st) red[tid] = fmaxf(red[tid], red[tid + st]);
        __syncthreads();
    }
    m = red[0];
    __syncthreads();

    float sum = 0.0f;
    for (int i = tid; i < TT; i += 256) {
        float e = __expf(buf[i] - m);
        buf[i] = e;
        sum += e;
    }
    red[tid] = sum;
    __syncthreads();
    #pragma unroll
    for (int st = 128; st > 0; st >>= 1) {
        if (tid < st) red[tid] += red[tid + st];
        __syncthreads();
    }
    const float inv = 1.0f / red[0];
    __syncthreads();

    __nv_bfloat162* ph2 = reinterpret_cast<__nv_bfloat162*>(Ph + row * TT);
    __nv_bfloat162* pl2 = reinterpret_cast<__nv_bfloat162*>(Pl + row * TT);
    for (int i = tid; i < TT / 2; i += 256) {
        float e0 = buf[2 * i] * inv;
        float e1 = buf[2 * i + 1] * inv;
        bf16 h0 = __float2bfloat16(e0), h1 = __float2bfloat16(e1);
        bf16 l0 = __float2bfloat16(e0 - __bfloat162float(h0));
        bf16 l1 = __float2bfloat16(e1 - __bfloat162float(h1));
        __nv_bfloat162 hp; hp.x = h0; hp.y = h1;
        __nv_bfloat162 lp; lp.x = l0; lp.y = l1;
        ph2[i] = hp;
        pl2[i] = lp;
    }
}

// ---------------------------------------------------------------------------
extern "C" void kernel_launch(void* const* d_in, const int* in_sizes, int n_in,
                              void* d_out, int out_size)
{
    const float* x  = (const float*)d_in[0];
    const float* Wq = (const float*)d_in[1];
    const float* Wk = (const float*)d_in[2];
    const float* Wv = (const float*)d_in[3];
    float* out = (float*)d_out;

    bf16 *xh, *xl, *wqh, *wql, *wkh, *wkl, *wvh, *wvl;
    bf16 *qh, *ql, *kh, *kl, *vh, *vl, *vth, *vtl, *phb, *plb;
    float* s;
    cudaGetSymbolAddress((void**)&xh, g_xh);   cudaGetSymbolAddress((void**)&xl, g_xl);
    cudaGetSymbolAddress((void**)&wqh, g_wqh); cudaGetSymbolAddress((void**)&wql, g_wql);
    cudaGetSymbolAddress((void**)&wkh, g_wkh); cudaGetSymbolAddress((void**)&wkl, g_wkl);
    cudaGetSymbolAddress((void**)&wvh, g_wvh); cudaGetSymbolAddress((void**)&wvl, g_wvl);
    cudaGetSymbolAddress((void**)&qh, g_qh);   cudaGetSymbolAddress((void**)&ql, g_ql);
    cudaGetSymbolAddress((void**)&kh, g_kh);   cudaGetSymbolAddress((void**)&kl, g_kl);
    cudaGetSymbolAddress((void**)&vh, g_vh);   cudaGetSymbolAddress((void**)&vl, g_vl);
    cudaGetSymbolAddress((void**)&vth, g_vth); cudaGetSymbolAddress((void**)&vtl, g_vtl);
    cudaGetSymbolAddress((void**)&s, g_s);
    cudaGetSymbolAddress((void**)&phb, g_ph);  cudaGetSymbolAddress((void**)&plb, g_pl);

    // 1) hi/lo splits of inputs
    {
        long long n4 = (long long)BB * TT * CC / 4;
        convert_hilo_kernel<<<(unsigned)((n4 + 255) / 256), 256>>>(
            (const float4*)x, (__nv_bfloat162*)xh, (__nv_bfloat162*)xl, n4);
        long long w4 = (long long)HH * CC / 4;
        convert_hilo_kernel<<<(unsigned)((w4 + 255) / 256), 256>>>(
            (const float4*)Wq, (__nv_bfloat162*)wqh, (__nv_bfloat162*)wql, w4);
        convert_hilo_kernel<<<(unsigned)((w4 + 255) / 256), 256>>>(
            (const float4*)Wk, (__nv_bfloat162*)wkh, (__nv_bfloat162*)wkl, w4);
        convert_hilo_kernel<<<(unsigned)((w4 + 255) / 256), 256>>>(
            (const float4*)Wv, (__nv_bfloat162*)wvh, (__nv_bfloat162*)wvl, w4);
    }

    // 2) projections: [BB*TT, HH] = x @ W^T  (hi/lo outputs)
    {
        dim3 g(HH / 128, (BB * TT) / 128, 1);   // (8, 256, 1)
        gemm_mma_kernel<1><<<g, 256>>>(xh, xl, wqh, wql, nullptr, qh, ql,
                                       BB * TT, HH, CC, 0, 0, 0, 1.0f);
        gemm_mma_kernel<1><<<g, 256>>>(xh, xl, wkh, wkl, nullptr, kh, kl,
                                       BB * TT, HH, CC, 0, 0, 0, 1.0f);
        gemm_mma_kernel<1><<<g, 256>>>(xh, xl, wvh, wvl, nullptr, vh, vl,
                                       BB * TT, HH, CC, 0, 0, 0, 1.0f);
    }

    // 3) transpose V per batch: vt[b][h][t] = v[b][t][h]
    {
        dim3 g(HH / 32, TT / 32, BB);
        transpose_hilo_kernel<<<g, dim3(32, 32, 1)>>>(vh, vl, vth, vtl);
    }

    // 4) scores: S_b = (Q_b @ K_b^T) / 32
    {
        dim3 g(TT / 128, TT / 128, BB);         // (32, 32, 8)
        gemm_mma_kernel<0><<<g, 256>>>(qh, ql, kh, kl, s, nullptr, nullptr,
                                       TT, TT, HH,
                                       (long long)TT * HH, (long long)TT * HH,
                                       (long long)TT * TT, 1.0f / 32.0f);
    }

    // 5) softmax -> P hi/lo
    softmax_kernel<<<BB * TT, 256>>>(s, phb, plb);

    // 6) out_b = P_b @ V_b^T-stored  (NT with vt[b][h][t])
    {
        dim3 g(HH / 128, TT / 128, BB);         // (8, 32, 8)
        gemm_mma_kernel<0><<<g, 256>>>(phb, plb, vth, vtl, out, nullptr, nullptr,
                                       TT, HH, TT,
                                       (long long)TT * TT, (long long)HH * TT,
                                       (long long)TT * HH, 1.0f);
    }
}

// round 4
// speedup vs baseline: 4.5023x; 1.3518x over previous
#include <cuda_runtime.h>
#include <cuda_bf16.h>
#include <math.h>
#include <stdint.h>

// Problem constants: B=8, T=4096, C=1024, H=1024
#define BB 8
#define TT 4096
#define CC 1024
#define HH 1024

typedef __nv_bfloat16 bf16;

// ---------------------------------------------------------------------------
// Static device scratch (no allocation allowed).
// ---------------------------------------------------------------------------
__device__ bf16 g_xh[(size_t)BB * TT * CC];
__device__ bf16 g_xl[(size_t)BB * TT * CC];
__device__ bf16 g_wqh[HH * CC], g_wql[HH * CC];
__device__ bf16 g_wkh[HH * CC], g_wkl[HH * CC];
__device__ bf16 g_wvh[HH * CC], g_wvl[HH * CC];
__device__ bf16 g_qh[(size_t)BB * TT * HH], g_ql[(size_t)BB * TT * HH];
__device__ bf16 g_kh[(size_t)BB * TT * HH], g_kl[(size_t)BB * TT * HH];
__device__ bf16 g_vh[(size_t)BB * TT * HH], g_vl[(size_t)BB * TT * HH];
// V transposed per batch: [b][h][t]
__device__ bf16 g_vth[(size_t)BB * HH * TT], g_vtl[(size_t)BB * HH * TT];
__device__ float g_s[(size_t)BB * TT * TT];
__device__ bf16 g_ph[(size_t)BB * TT * TT], g_pl[(size_t)BB * TT * TT];

// ---------------------------------------------------------------------------
// helpers
// ---------------------------------------------------------------------------
__device__ __forceinline__ uint32_t smem_u32(const void* p) {
    uint32_t a;
    asm("{ .reg .u64 t; cvta.to.shared.u64 t, %1; cvt.u32.u64 %0, t; }"
        : "=r"(a) : "l"(p));
    return a;
}
__device__ __forceinline__ void cp_async16(uint32_t s, const void* g) {
    asm volatile("cp.async.cg.shared.global [%0], [%1], 16;" :: "r"(s), "l"(g));
}
#define CP_COMMIT() asm volatile("cp.async.commit_group;" ::: "memory")
#define CP_WAIT1()  asm volatile("cp.async.wait_group 1;" ::: "memory")

// m16n8k16 bf16 MMA (base ISA)
__device__ __forceinline__ void mma16816(float* c, const uint32_t* a,
                                         uint32_t b0, uint32_t b1)
{
    asm volatile(
        "mma.sync.aligned.m16n8k16.row.col.f32.bf16.bf16.f32 "
        "{%0,%1,%2,%3}, {%4,%5,%6,%7}, {%8,%9}, {%0,%1,%2,%3};"
        : "+f"(c[0]), "+f"(c[1]), "+f"(c[2]), "+f"(c[3])
        : "r"(a[0]), "r"(a[1]), "r"(a[2]), "r"(a[3]), "r"(b0), "r"(b1));
}

// ---------------------------------------------------------------------------
// bf16x3 NT GEMM:  D[M,N] = alpha * (A[M,K] @ B[N,K]^T)
// A,B as (hi,lo) bf16 pairs; D = Ah*Bh + Ah*Bl + Al*Bh in fp32 accum.
// CTA tile 128x128x32.  256 threads = 8 warps (4M x 2N), warp tile 32x64.
// cp.async double-buffered smem (2 stages x 40960 B), 2 CTAs/SM.
// Smem rows padded to 80 B: 16B-aligned STS + conflict-free 32-bit LDS.
// EPI: 0 = fp32*alpha -> outF ;  1 = hi/lo bf16 -> outH/outL (row-major).
// ---------------------------------------------------------------------------
constexpr int STAGE = 40960;                 // 4 tiles x 128 rows x 80 B
constexpr int T_AH = 0, T_AL = 10240, T_BH = 20480, T_BL = 30720;

template <int EPI>
__global__ __launch_bounds__(256, 2) void gemm_mma_kernel(
    const bf16* __restrict__ Ah, const bf16* __restrict__ Al,
    const bf16* __restrict__ Bh, const bf16* __restrict__ Bl,
    float* __restrict__ outF, bf16* __restrict__ outH, bf16* __restrict__ outL,
    int M, int N, int K,
    long long sA, long long sB, long long sC, float alpha)
{
    extern __shared__ __align__(16) unsigned char sm[];
    const uint32_t sbase = smem_u32(sm);

    const int tid = threadIdx.x;
    const int wid = tid >> 5;
    const int lane = tid & 31;
    const int g = lane >> 2;      // row-in-frag group
    const int t = lane & 3;       // k-pair / col pair
    const int wm = wid & 3;       // warp M (0..3) -> rows wm*32
    const int wn = wid >> 2;      // warp N (0..1) -> cols wn*64

    const long long bz = blockIdx.z;
    Ah += bz * sA;  Al += bz * sA;
    Bh += bz * sB;  Bl += bz * sB;

    const int bm = blockIdx.y * 128;
    const int bn = blockIdx.x * 128;
    const int nk = K >> 5;        // K / 32

    // loader mapping: 512 uint4 slots/tile; thread owns slots tid, tid+256
    const int lrow = tid >> 2;          // 0..63 (+64 second slot)
    const int lc4  = tid & 3;
    const uint32_t so0 = (uint32_t)(lrow * 80 + lc4 * 16);
    const uint32_t so1 = so0 + 64u * 80u;

    auto issue_stage = [&](int kt, int buf) {
        const uint32_t st = sbase + (uint32_t)buf * STAGE;
        const size_t ka = (size_t)kt * 32 + lc4 * 8;
        const size_t a0 = (size_t)(bm + lrow) * K + ka;
        const size_t a1 = (size_t)(bm + lrow + 64) * K + ka;
        const size_t b0 = (size_t)(bn + lrow) * K + ka;
        const size_t b1 = (size_t)(bn + lrow + 64) * K + ka;
        cp_async16(st + T_AH + so0, Ah + a0);
        cp_async16(st + T_AH + so1, Ah + a1);
        cp_async16(st + T_AL + so0, Al + a0);
        cp_async16(st + T_AL + so1, Al + a1);
        cp_async16(st + T_BH + so0, Bh + b0);
        cp_async16(st + T_BH + so1, Bh + b1);
        cp_async16(st + T_BL + so0, Bl + b0);
        cp_async16(st + T_BL + so1, Bl + b1);
    };

    float acc[2][8][4];
    #pragma unroll
    for (int mt = 0; mt < 2; mt++)
        #pragma unroll
        for (int nt = 0; nt < 8; nt++)
            #pragma unroll
            for (int i = 0; i < 4; i++) acc[mt][nt][i] = 0.0f;

    issue_stage(0, 0);
    CP_COMMIT();

    for (int kt = 0; kt < nk; kt++) {
        if (kt + 1 < nk) issue_stage(kt + 1, (kt + 1) & 1);
        CP_COMMIT();
        CP_WAIT1();
        __syncthreads();

        const unsigned char* smp = sm + (kt & 1) * STAGE;

        #pragma unroll
        for (int ks = 0; ks < 2; ks++) {
            uint32_t ah[2][4], al[2][4];
            #pragma unroll
            for (int mt = 0; mt < 2; mt++) {
                const int arow = wm * 32 + mt * 16 + g;
                const unsigned char* pa = smp + arow * 80 + ks * 32 + t * 4;
                ah[mt][0] = *reinterpret_cast<const uint32_t*>(pa + T_AH);
                ah[mt][1] = *reinterpret_cast<const uint32_t*>(pa + T_AH + 8 * 80);
                ah[mt][2] = *reinterpret_cast<const uint32_t*>(pa + T_AH + 16);
                ah[mt][3] = *reinterpret_cast<const uint32_t*>(pa + T_AH + 8 * 80 + 16);
                al[mt][0] = *reinterpret_cast<const uint32_t*>(pa + T_AL);
                al[mt][1] = *reinterpret_cast<const uint32_t*>(pa + T_AL + 8 * 80);
                al[mt][2] = *reinterpret_cast<const uint32_t*>(pa + T_AL + 16);
                al[mt][3] = *reinterpret_cast<const uint32_t*>(pa + T_AL + 8 * 80 + 16);
            }
            #pragma unroll
            for (int nt = 0; nt < 8; nt++) {
                const int brow = wn * 64 + nt * 8 + g;
                const unsigned char* pb = smp + brow * 80 + ks * 32 + t * 4;
                const uint32_t bh0 = *reinterpret_cast<const uint32_t*>(pb + T_BH);
                const uint32_t bh1 = *reinterpret_cast<const uint32_t*>(pb + T_BH + 16);
                const uint32_t bl0 = *reinterpret_cast<const uint32_t*>(pb + T_BL);
                const uint32_t bl1 = *reinterpret_cast<const uint32_t*>(pb + T_BL + 16);
                #pragma unroll
                for (int mt = 0; mt < 2; mt++) {
                    mma16816(acc[mt][nt], ah[mt], bh0, bh1);
                    mma16816(acc[mt][nt], ah[mt], bl0, bl1);
                    mma16816(acc[mt][nt], al[mt], bh0, bh1);
                }
            }
        }
        __syncthreads();
    }

    // ---- epilogue ----
    #pragma unroll
    for (int mt = 0; mt < 2; mt++) {
        const int r0 = bm + wm * 32 + mt * 16 + g;
        #pragma unroll
        for (int nt = 0; nt < 8; nt++) {
            const int c0 = bn + wn * 64 + nt * 8 + 2 * t;
            if (EPI == 0) {
                float2 v0, v1;
                v0.x = alpha * acc[mt][nt][0]; v0.y = alpha * acc[mt][nt][1];
                v1.x = alpha * acc[mt][nt][2]; v1.y = alpha * acc[mt][nt][3];
                *reinterpret_cast<float2*>(outF + bz * sC + (size_t)r0 * N + c0) = v0;
                *reinterpret_cast<float2*>(outF + bz * sC + (size_t)(r0 + 8) * N + c0) = v1;
            } else {
                #pragma unroll
                for (int h = 0; h < 2; h++) {
                    const float v0 = acc[mt][nt][2 * h + 0];
                    const float v1 = acc[mt][nt][2 * h + 1];
                    bf16 h0 = __float2bfloat16(v0);
                    bf16 h1 = __float2bfloat16(v1);
                    bf16 l0 = __float2bfloat16(v0 - __bfloat162float(h0));
                    bf16 l1 = __float2bfloat16(v1 - __bfloat162float(h1));
                    __nv_bfloat162 hp; hp.x = h0; hp.y = h1;
                    __nv_bfloat162 lp; lp.x = l0; lp.y = l1;
                    const size_t off = (size_t)(r0 + 8 * h) * N + c0;
                    *reinterpret_cast<__nv_bfloat162*>(outH + off) = hp;
                    *reinterpret_cast<__nv_bfloat162*>(outL + off) = lp;
                }
            }
        }
    }
}

// ---------------------------------------------------------------------------
// fp32 -> (hi, lo) bf16 split, float4-vectorized.  n4 = n/4.
// ---------------------------------------------------------------------------
__global__ __launch_bounds__(256) void convert_hilo_kernel(
    const float4* __restrict__ in, __nv_bfloat162* __restrict__ h2,
    __nv_bfloat162* __restrict__ l2, long long n4)
{
    long long i = (long long)blockIdx.x * blockDim.x + threadIdx.x;
    if (i >= n4) return;
    float4 v = in[i];
    bf16 h0 = __float2bfloat16(v.x), h1 = __float2bfloat16(v.y);
    bf16 h2v = __float2bfloat16(v.z), h3 = __float2bfloat16(v.w);
    bf16 l0 = __float2bfloat16(v.x - __bfloat162float(h0));
    bf16 l1 = __float2bfloat16(v.y - __bfloat162float(h1));
    bf16 l2v = __float2bfloat16(v.z - __bfloat162float(h2v));
    bf16 l3 = __float2bfloat16(v.w - __bfloat162float(h3));
    __nv_bfloat162 a; a.x = h0; a.y = h1;
    __nv_bfloat162 b; b.x = h2v; b.y = h3;
    __nv_bfloat162 c; c.x = l0; c.y = l1;
    __nv_bfloat162 d; d.x = l2v; d.y = l3;
    h2[2 * i] = a; h2[2 * i + 1] = b;
    l2[2 * i] = c; l2[2 * i + 1] = d;
}

// ---------------------------------------------------------------------------
// Per-batch transpose of hi/lo V: out[b][h][t] = in[b][t][h]
// ---------------------------------------------------------------------------
__global__ __launch_bounds__(1024) void transpose_hilo_kernel(
    const bf16* __restrict__ ih, const bf16* __restrict__ il,
    bf16* __restrict__ oh, bf16* __restrict__ ol)
{
    __shared__ bf16 th[32][33];
    __shared__ bf16 tl[32][33];
    const int b = blockIdx.z;
    const int h0 = blockIdx.x * 32;
    const int t0 = blockIdx.y * 32;
    const int tx = threadIdx.x, ty = threadIdx.y;

    const size_t iin = ((size_t)b * TT + t0 + ty) * HH + h0 + tx;
    th[ty][tx] = ih[iin];
    tl[ty][tx] = il[iin];
    __syncthreads();
    const size_t iout = ((size_t)b * HH + h0 + ty) * TT + t0 + tx;
    oh[iout] = th[tx][ty];
    ol[iout] = tl[tx][ty];
}

// ---------------------------------------------------------------------------
// Row softmax over S (fp32, rows of TT) -> P as (hi, lo) bf16.
// ---------------------------------------------------------------------------
__global__ __launch_bounds__(256) void softmax_kernel(
    const float* __restrict__ S, bf16* __restrict__ Ph, bf16* __restrict__ Pl)
{
    __shared__ float buf[TT];
    __shared__ float red[256];
    const size_t row = blockIdx.x;
    const float4* p4 = reinterpret_cast<const float4*>(S + row * TT);
    const int tid = threadIdx.x;

    float m = -INFINITY;
    for (int i = tid; i < TT / 4; i += 256) {
        float4 v = p4[i];
        reinterpret_cast<float4*>(buf)[i] = v;
        m = fmaxf(m, fmaxf(fmaxf(v.x, v.y), fmaxf(v.z, v.w)));
    }
    red[tid] = m;
    __syncthreads();
    #pragma unroll
    for (int st = 128; st > 0; st >>= 1) {
        if (tid < st) red[tid] = fmaxf(red[tid], red[tid + st]);
        __syncthreads();
    }
    m = red[0];
    __syncthreads();

    float sum = 0.0f;
    for (int i = tid; i < TT; i += 256) {
        float e = __expf(buf[i] - m);
        buf[i] = e;
        sum += e;
    }
    red[tid] = sum;
    __syncthreads();
    #pragma unroll
    for (int st = 128; st > 0; st >>= 1) {
        if (tid < st) red[tid] += red[tid + st];
        __syncthreads();
    }
    const float inv = 1.0f / red[0];
    __syncthreads();

    __nv_bfloat162* ph2 = reinterpret_cast<__nv_bfloat162*>(Ph + row * TT);
    __nv_bfloat162* pl2 = reinterpret_cast<__nv_bfloat162*>(Pl + row * TT);
    for (int i = tid; i < TT / 2; i += 256) {
        float e0 = buf[2 * i] * inv;
        float e1 = buf[2 * i + 1] * inv;
        bf16 h0 = __float2bfloat16(e0), h1 = __float2bfloat16(e1);
        bf16 l0 = __float2bfloat16(e0 - __bfloat162float(h0));
        bf16 l1 = __float2bfloat16(e1 - __bfloat162float(h1));
        __nv_bfloat162 hp; hp.x = h0; hp.y = h1;
        __nv_bfloat162 lp; lp.x = l0; lp.y = l1;
        ph2[i] = hp;
        pl2[i] = lp;
    }
}

// ---------------------------------------------------------------------------
extern "C" void kernel_launch(void* const* d_in, const int* in_sizes, int n_in,
                              void* d_out, int out_size)
{
    const float* x  = (const float*)d_in[0];
    const float* Wq = (const float*)d_in[1];
    const float* Wk = (const float*)d_in[2];
    const float* Wv = (const float*)d_in[3];
    float* out = (float*)d_out;

    bf16 *xh, *xl, *wqh, *wql, *wkh, *wkl, *wvh, *wvl;
    bf16 *qh, *ql, *kh, *kl, *vh, *vl, *vth, *vtl, *phb, *plb;
    float* s;
    cudaGetSymbolAddress((void**)&xh, g_xh);   cudaGetSymbolAddress((void**)&xl, g_xl);
    cudaGetSymbolAddress((void**)&wqh, g_wqh); cudaGetSymbolAddress((void**)&wql, g_wql);
    cudaGetSymbolAddress((void**)&wkh, g_wkh); cudaGetSymbolAddress((void**)&wkl, g_wkl);
    cudaGetSymbolAddress((void**)&wvh, g_wvh); cudaGetSymbolAddress((void**)&wvl, g_wvl);
    cudaGetSymbolAddress((void**)&qh, g_qh);   cudaGetSymbolAddress((void**)&ql, g_ql);
    cudaGetSymbolAddress((void**)&kh, g_kh);   cudaGetSymbolAddress((void**)&kl, g_kl);
    cudaGetSymbolAddress((void**)&vh, g_vh);   cudaGetSymbolAddress((void**)&vl, g_vl);
    cudaGetSymbolAddress((void**)&vth, g_vth); cudaGetSymbolAddress((void**)&vtl, g_vtl);
    cudaGetSymbolAddress((void**)&s, g_s);
    cudaGetSymbolAddress((void**)&phb, g_ph);  cudaGetSymbolAddress((void**)&plb, g_pl);

    const int DSMEM = 2 * STAGE;   // 81920 B
    static bool attr_done = false;
    if (!attr_done) {
        cudaFuncSetAttribute(gemm_mma_kernel<0>,
                             cudaFuncAttributeMaxDynamicSharedMemorySize, DSMEM);
        cudaFuncSetAttribute(gemm_mma_kernel<1>,
                             cudaFuncAttributeMaxDynamicSharedMemorySize, DSMEM);
        attr_done = true;
    }

    // 1) hi/lo splits of inputs
    {
        long long n4 = (long long)BB * TT * CC / 4;
        convert_hilo_kernel<<<(unsigned)((n4 + 255) / 256), 256>>>(
            (const float4*)x, (__nv_bfloat162*)xh, (__nv_bfloat162*)xl, n4);
        long long w4 = (long long)HH * CC / 4;
        convert_hilo_kernel<<<(unsigned)((w4 + 255) / 256), 256>>>(
            (const float4*)Wq, (__nv_bfloat162*)wqh, (__nv_bfloat162*)wql, w4);
        convert_hilo_kernel<<<(unsigned)((w4 + 255) / 256), 256>>>(
            (const float4*)Wk, (__nv_bfloat162*)wkh, (__nv_bfloat162*)wkl, w4);
        convert_hilo_kernel<<<(unsigned)((w4 + 255) / 256), 256>>>(
            (const float4*)Wv, (__nv_bfloat162*)wvh, (__nv_bfloat162*)wvl, w4);
    }

    // 2) projections: [BB*TT, HH] = x @ W^T  (hi/lo outputs)
    {
        dim3 g(HH / 128, (BB * TT) / 128, 1);
        gemm_mma_kernel<1><<<g, 256, DSMEM>>>(xh, xl, wqh, wql, nullptr, qh, ql,
                                              BB * TT, HH, CC, 0, 0, 0, 1.0f);
        gemm_mma_kernel<1><<<g, 256, DSMEM>>>(xh, xl, wkh, wkl, nullptr, kh, kl,
                                              BB * TT, HH, CC, 0, 0, 0, 1.0f);
        gemm_mma_kernel<1><<<g, 256, DSMEM>>>(xh, xl, wvh, wvl, nullptr, vh, vl,
                                              BB * TT, HH, CC, 0, 0, 0, 1.0f);
    }

    // 3) transpose V per batch: vt[b][h][t] = v[b][t][h]
    {
        dim3 g(HH / 32, TT / 32, BB);
        transpose_hilo_kernel<<<g, dim3(32, 32, 1)>>>(vh, vl, vth, vtl);
    }

    // 4) scores: S_b = (Q_b @ K_b^T) / 32
    {
        dim3 g(TT / 128, TT / 128, BB);
        gemm_mma_kernel<0><<<g, 256, DSMEM>>>(qh, ql, kh, kl, s, nullptr, nullptr,
                                              TT, TT, HH,
                                              (long long)TT * HH, (long long)TT * HH,
                                              (long long)TT * TT, 1.0f / 32.0f);
    }

    // 5) softmax -> P hi/lo
    softmax_kernel<<<BB * TT, 256>>>(s, phb, plb);

    // 6) out_b = P_b @ V_b  (NT with vt[b][h][t])
    {
        dim3 g(HH / 128, TT / 128, BB);
        gemm_mma_kernel<0><<<g, 256, DSMEM>>>(phb, plb, vth, vtl, out, nullptr, nullptr,
                                              TT, HH, TT,
                                              (long long)TT * TT, (long long)HH * TT,
                                              (long long)TT * HH, 1.0f);
    }
}